// round 15
// baseline (speedup 1.0000x reference)
#include <cuda_runtime.h>
#include <cstdint>

#define B_SZ   32
#define N_E    500000
#define N_T    2000000
#define N_R    200
#define N_W2V  300

// Scratch: entity-major buffers [N_E][32] (buf0 = T(x), buf_k = result after hop k)
// and r activations [3][N_R][32]
__device__ float g_buf0[(size_t)N_E * B_SZ];
__device__ float g_buf1[(size_t)N_E * B_SZ];
__device__ float g_buf2[(size_t)N_E * B_SZ];
__device__ float g_buf3[(size_t)N_E * B_SZ];
__device__ float g_rt[3 * N_R * B_SZ];

#define ZERO_BLOCKS 15625   // 4M float4 / 256 threads

// ---------------------------------------------------------------------------
// Fused prologue, one launch, 256-thread blocks, dispatch on blockIdx.x:
//   [0, 300)           : rmlp — 2 (hop,rel) tasks per block, 4 warps per task
//                        (k-loop split 75/warp, smem-reduced). FIRST so the
//                        serial-latency work starts in wave 0, not the tail.
//   [300, 300+15625)   : zero buf1 (hop1's destination)
//   [.., +15625)       : transpose x [32,N_E] -> buf0 [N_E,32]
// Sections touch disjoint memory; no intra-launch ordering needed.
// ---------------------------------------------------------------------------
#define PRE_RMLP_BLOCKS 300     // 600 tasks / 2 per block
#define PRE_TIN_BLOCKS  15625
#define PRE_TOTAL_BLOCKS (PRE_RMLP_BLOCKS + ZERO_BLOCKS + PRE_TIN_BLOCKS)

__global__ void __launch_bounds__(256)
fused_pre_kernel(const float* __restrict__ x, const float* __restrict__ q,
                 const float* __restrict__ W1, const float* __restrict__ b1,
                 const float* __restrict__ W2, const float* __restrict__ b2,
                 const float* __restrict__ W3, const float* __restrict__ b3,
                 float* __restrict__ buf0, float4* __restrict__ z1,
                 float* __restrict__ rt) {
    int bid = blockIdx.x;
    int tid = threadIdx.x;

    if (bid < PRE_RMLP_BLOCKS) {
        // ---- rmlp section ----
        __shared__ float partial[2][4][32];
        int task   = tid >> 7;            // 0..1 within block
        int wg_tid = tid & 127;
        int wip    = wg_tid >> 5;         // warp in task: 0..3
        int lane   = tid & 31;            // batch
        int gt     = bid * 2 + task;      // global (hop,rel) task: 0..599
        int hop    = gt / N_R;
        int rel    = gt - hop * N_R;

        const float* W = (hop == 0) ? W1 : (hop == 1) ? W2 : W3;
        const float* b = (hop == 0) ? b1 : (hop == 1) ? b2 : b3;

        // each warp covers k in [wip*75, wip*75+75)
        int k0 = wip * 75;
        const float* qrow = q + (size_t)lane * N_W2V;
        float a0 = 0.f, a1 = 0.f, a2 = 0.f;
#pragma unroll
        for (int k = 0; k < 75; k += 3) {
            a0 = fmaf(qrow[k0 + k + 0], __ldg(W + (size_t)(k0 + k + 0) * N_R + rel), a0);
            a1 = fmaf(qrow[k0 + k + 1], __ldg(W + (size_t)(k0 + k + 1) * N_R + rel), a1);
            a2 = fmaf(qrow[k0 + k + 2], __ldg(W + (size_t)(k0 + k + 2) * N_R + rel), a2);
        }
        partial[task][wip][lane] = a0 + a1 + a2;
        __syncthreads();

        if (wg_tid < 32) {
            float acc = b[rel] + partial[task][0][lane] + partial[task][1][lane]
                      + partial[task][2][lane] + partial[task][3][lane];
            rt[((size_t)hop * N_R + rel) * B_SZ + lane] = acc;
        }
        return;
    }

    if (bid < PRE_RMLP_BLOCKS + ZERO_BLOCKS) {
        size_t i = (size_t)(bid - PRE_RMLP_BLOCKS) * 256 + tid;
        z1[i] = make_float4(0.f, 0.f, 0.f, 0.f);
        return;
    }

    // ---- transpose-in section: 32 entities per block ----
    {
        __shared__ float tile[32][33];
        int e0 = (bid - PRE_RMLP_BLOCKS - ZERO_BLOCKS) * 32;
        int tx = tid & 31;
        int row = tid >> 5;       // 0..7
#pragma unroll
        for (int p = 0; p < 4; p++) {
            int b = row + p * 8;
            tile[b][tx] = x[(size_t)b * N_E + e0 + tx];
        }
        __syncthreads();
#pragma unroll
        for (int p = 0; p < 4; p++) {
            int j = row + p * 8;
            buf0[(size_t)(e0 + j) * 32 + tx] = tile[tx][j];
        }
    }
}

// ---------------------------------------------------------------------------
// Transpose selected buffer [N_E, 32] -> out [32, N_E].
// Source buffer chosen device-side from *n_hop (0..3).
// ---------------------------------------------------------------------------
__global__ void transpose_out_kernel(const float* __restrict__ b0,
                                     const float* __restrict__ b1,
                                     const float* __restrict__ b2,
                                     const float* __restrict__ b3,
                                     const int* __restrict__ n_hop,
                                     float* __restrict__ out) {
    __shared__ float tile[32][33];
    int nh = *n_hop;
    nh = nh < 0 ? 0 : (nh > 3 ? 3 : nh);
    const float* wt = (nh == 0) ? b0 : (nh == 1) ? b1 : (nh == 2) ? b2 : b3;

    int e0 = blockIdx.x * 32;
    int tx = threadIdx.x, ty = threadIdx.y;
    tile[ty][tx] = wt[(size_t)(e0 + ty) * 32 + tx];
    __syncthreads();
    out[(size_t)ty * N_E + e0 + tx] = tile[tx][ty];
}

// ---------------------------------------------------------------------------
// One hop: for each triple t:  dst[:, obj[t]] += src[:, subj[t]] * r[:, rel[t]]
// Entity-major layout: src/dst are [N_E][32]. Each octet of 8 lanes handles
// TPO=4 consecutive triples (original random order — measured best for both
// the gather and the RED streams); per lane one float4 (4 of the 32 batches).
//
// When zbuf != null, the grid is 2*HOP_BLOCKS and zero blocks are
// INTERLEAVED (odd bids) with hop blocks (even bids) so every wave mixes
// streaming stores with the latency-bound gather/RED work — the zero of the
// next hop's destination rides in the hop's idle bandwidth instead of
// running as trailing waves.
// ---------------------------------------------------------------------------
#define TPO 4   // triples per octet
#define HOP_BLOCKS 15625   // N_T * 8 / TPO / 256

__global__ void __launch_bounds__(256)
hop_kernel(const float* __restrict__ src, float* __restrict__ dst,
           const int* __restrict__ subj, const int* __restrict__ rel,
           const int* __restrict__ obj, const float* __restrict__ rt,
           const int* __restrict__ n_hop, int hop,
           float4* __restrict__ zbuf) {
    if (*n_hop < hop) return;

    int bid = blockIdx.x;
    int tid = threadIdx.x;
    int work;

    if (zbuf != nullptr) {
        if (bid & 1) {
            // ---- interleaved zero of next hop's destination (disjoint) ----
            size_t i = (size_t)(bid >> 1) * 256 + tid;
            zbuf[i] = make_float4(0.f, 0.f, 0.f, 0.f);
            return;
        }
        work = bid >> 1;
    } else {
        work = bid;
    }

    int lane = tid & 31;
    int sub  = lane & 7;                                    // which float4 of 32 batches
    int oct  = (int)(((size_t)work * 256 + tid) >> 3);      // octet id
    int t0   = oct * TPO;
    if (t0 >= N_T) return;

    // 4 triples' indices via one int4 load per array (t0 % 4 == 0)
    int4 sA = __ldg(reinterpret_cast<const int4*>(subj + t0));
    int4 rA = __ldg(reinterpret_cast<const int4*>(rel + t0));
    int4 oA = __ldg(reinterpret_cast<const int4*>(obj + t0));

    int s[TPO]  = {sA.x, sA.y, sA.z, sA.w};
    int rl[TPO] = {rA.x, rA.y, rA.z, rA.w};
    int o[TPO]  = {oA.x, oA.y, oA.z, oA.w};

    const float4* src4 = reinterpret_cast<const float4*>(src);
    const float4* rt4  = reinterpret_cast<const float4*>(rt);
    float4* dst4       = reinterpret_cast<float4*>(dst);

    // front-batch all long-latency gathers
    float4 a[TPO];
#pragma unroll
    for (int j = 0; j < TPO; j++) a[j] = __ldg(src4 + (size_t)s[j] * 8 + sub);

    // r-vector loads are hot in L1 (25.6 KB table)
    float4 r4[TPO];
#pragma unroll
    for (int j = 0; j < TPO; j++) r4[j] = __ldg(rt4 + (size_t)rl[j] * 8 + sub);

#pragma unroll
    for (int j = 0; j < TPO; j++) {
        float4 m = make_float4(a[j].x * r4[j].x, a[j].y * r4[j].y,
                               a[j].z * r4[j].z, a[j].w * r4[j].w);
        float4* d = dst4 + (size_t)o[j] * 8 + sub;
        asm volatile("red.global.add.v4.f32 [%0], {%1, %2, %3, %4};"
                     :: "l"(d), "f"(m.x), "f"(m.y), "f"(m.z), "f"(m.w)
                     : "memory");
    }
}

// ---------------------------------------------------------------------------
// kernel_launch
// Input order (metadata): x, q, subj_idx, rel_idx, obj_idx, W1, b1, W2, b2, W3, b3, n_hop
// ---------------------------------------------------------------------------
extern "C" void kernel_launch(void* const* d_in, const int* in_sizes, int n_in,
                              void* d_out, int out_size) {
    const float* x     = (const float*)d_in[0];
    const float* q     = (const float*)d_in[1];
    const int* subj    = (const int*)d_in[2];
    const int* rel     = (const int*)d_in[3];
    const int* obj     = (const int*)d_in[4];
    const float* W1    = (const float*)d_in[5];
    const float* b1    = (const float*)d_in[6];
    const float* W2    = (const float*)d_in[7];
    const float* b2    = (const float*)d_in[8];
    const float* W3    = (const float*)d_in[9];
    const float* b3    = (const float*)d_in[10];
    const int* n_hop   = (const int*)d_in[11];
    float* out         = (float*)d_out;

    float *buf0, *buf1, *buf2, *buf3, *rt;
    cudaGetSymbolAddress((void**)&buf0, g_buf0);
    cudaGetSymbolAddress((void**)&buf1, g_buf1);
    cudaGetSymbolAddress((void**)&buf2, g_buf2);
    cudaGetSymbolAddress((void**)&buf3, g_buf3);
    cudaGetSymbolAddress((void**)&rt, g_rt);

    // prologue: rmlp (first) + zero buf1 + transpose-in, one launch
    fused_pre_kernel<<<PRE_TOTAL_BLOCKS, 256>>>(
        x, q, W1, b1, W2, b2, W3, b3, buf0, (float4*)buf1, rt);

    // hop1 zeroes buf2 (interleaved); hop2 zeroes buf3; hop3 has no zero work
    hop_kernel<<<2 * HOP_BLOCKS, 256>>>(
        buf0, buf1, subj, rel, obj, rt + 0 * N_R * B_SZ, n_hop, 1, (float4*)buf2);
    hop_kernel<<<2 * HOP_BLOCKS, 256>>>(
        buf1, buf2, subj, rel, obj, rt + 1 * N_R * B_SZ, n_hop, 2, (float4*)buf3);
    hop_kernel<<<HOP_BLOCKS, 256>>>(
        buf2, buf3, subj, rel, obj, rt + 2 * N_R * B_SZ, n_hop, 3, nullptr);

    // back to [B, N_E], selecting the buffer that matches n_hop
    transpose_out_kernel<<<N_E / 32, dim3(32, 32)>>>(buf0, buf1, buf2, buf3, n_hop, out);
}

// round 16
// speedup vs baseline: 1.4501x; 1.4501x over previous
#include <cuda_runtime.h>
#include <cuda_fp16.h>
#include <cstdint>
#include <cstring>

#define B_SZ   32
#define N_E    500000
#define N_T    2000000
#define N_R    200
#define N_W2V  300

__device__ __half g_buf0h[(size_t)N_E * B_SZ];
__device__ __half g_buf1h[(size_t)N_E * B_SZ];
__device__ __half g_buf2h[(size_t)N_E * B_SZ];
__device__ float  g_buf3 [(size_t)N_E * B_SZ];
__device__ float  g_rt[3 * N_R * B_SZ];

#define Z16_F4     2000000
#define Z32_F4     4000000
#define Z16_BLOCKS 7813
#define Z32_BLOCKS 15625

#define PRE_RMLP_BLOCKS 300
#define PRE_TIN_BLOCKS  15625
#define PRE_TOTAL_BLOCKS (PRE_RMLP_BLOCKS + Z16_BLOCKS + PRE_TIN_BLOCKS)

__global__ void __launch_bounds__(256)
fused_pre_kernel(const float* __restrict__ x, const float* __restrict__ q,
                 const float* __restrict__ W1, const float* __restrict__ b1,
                 const float* __restrict__ W2, const float* __restrict__ b2,
                 const float* __restrict__ W3, const float* __restrict__ b3,
                 __half* __restrict__ buf0h, float4* __restrict__ z1,
                 float* __restrict__ rt) {
    int bid = blockIdx.x;
    int tid = threadIdx.x;

    if (bid < PRE_RMLP_BLOCKS) {
        __shared__ float partial[2][4][32];
        int task   = tid >> 7;
        int wg_tid = tid & 127;
        int wip    = wg_tid >> 5;
        int lane   = tid & 31;
        int gt     = bid * 2 + task;
        int hop    = gt / N_R;
        int rel    = gt - hop * N_R;

        const float* W = (hop == 0) ? W1 : (hop == 1) ? W2 : W3;
        const float* b = (hop == 0) ? b1 : (hop == 1) ? b2 : b3;

        int k0 = wip * 75;
        const float* qrow = q + (size_t)lane * N_W2V;
        float a0 = 0.f, a1 = 0.f, a2 = 0.f;
#pragma unroll
        for (int k = 0; k < 75; k += 3) {
            a0 = fmaf(qrow[k0 + k + 0], __ldg(W + (size_t)(k0 + k + 0) * N_R + rel), a0);
            a1 = fmaf(qrow[k0 + k + 1], __ldg(W + (size_t)(k0 + k + 1) * N_R + rel), a1);
            a2 = fmaf(qrow[k0 + k + 2], __ldg(W + (size_t)(k0 + k + 2) * N_R + rel), a2);
        }
        partial[task][wip][lane] = a0 + a1 + a2;
        __syncthreads();

        if (wg_tid < 32) {
            float acc = b[rel] + partial[task][0][lane] + partial[task][1][lane]
                      + partial[task][2][lane] + partial[task][3][lane];
            rt[((size_t)hop * N_R + rel) * B_SZ + lane] = acc;
        }
        return;
    }

    if (bid < PRE_RMLP_BLOCKS + Z16_BLOCKS) {
        size_t i = (size_t)(bid - PRE_RMLP_BLOCKS) * 256 + tid;
        if (i < Z16_F4) z1[i] = make_float4(0.f, 0.f, 0.f, 0.f);
        return;
    }

    {
        __shared__ float tile[32][33];
        int e0 = (bid - PRE_RMLP_BLOCKS - Z16_BLOCKS) * 32;
        int tx = tid & 31;
        int row = tid >> 5;
#pragma unroll
        for (int p = 0; p < 4; p++) {
            int b = row + p * 8;
            tile[b][tx] = x[(size_t)b * N_E + e0 + tx];
        }
        __syncthreads();
#pragma unroll
        for (int p = 0; p < 4; p++) {
            int j = row + p * 8;
            buf0h[(size_t)(e0 + j) * 32 + tx] = __float2half_rn(tile[tx][j]);
        }
    }
}

__global__ void transpose_out_kernel(const __half* __restrict__ b0h,
                                     const __half* __restrict__ b1h,
                                     const __half* __restrict__ b2h,
                                     const float* __restrict__ b3,
                                     const int* __restrict__ n_hop,
                                     float* __restrict__ out) {
    __shared__ float tile[32][33];
    int nh = *n_hop;
    nh = nh < 0 ? 0 : (nh > 3 ? 3 : nh);

    int e0 = blockIdx.x * 32;
    int tx = threadIdx.x, ty = threadIdx.y;

    float v;
    if (nh == 3) {
        v = b3[(size_t)(e0 + ty) * 32 + tx];
    } else {
        const __half* bh = (nh == 0) ? b0h : (nh == 1) ? b1h : b2h;
        v = __half2float(bh[(size_t)(e0 + ty) * 32 + tx]);
    }
    tile[ty][tx] = v;
    __syncthreads();
    out[(size_t)ty * N_E + e0 + tx] = tile[tx][ty];
}

#define TPO 4
#define H12_BLOCKS 7813

__global__ void __launch_bounds__(256)
hop12_kernel(const __half* __restrict__ src, __half* __restrict__ dst,
             const int* __restrict__ subj, const int* __restrict__ rel,
             const int* __restrict__ obj, const float* __restrict__ rt,
             const int* __restrict__ n_hop, int hop,
             float4* __restrict__ zbuf, int zn) {
    if (*n_hop < hop) return;

    int bid = blockIdx.x;
    int tid = threadIdx.x;

    if (bid >= H12_BLOCKS) {
        size_t i = (size_t)(bid - H12_BLOCKS) * 256 + tid;
        if (i < (size_t)zn) zbuf[i] = make_float4(0.f, 0.f, 0.f, 0.f);
        return;
    }

    int lane = tid & 31;
    int sub  = lane & 3;
    int qid  = (int)(((size_t)bid * 256 + tid) >> 2);
    int t0   = qid * TPO;
    if (t0 >= N_T) return;

    int4 sA = __ldg(reinterpret_cast<const int4*>(subj + t0));
    int4 rA = __ldg(reinterpret_cast<const int4*>(rel + t0));
    int4 oA = __ldg(reinterpret_cast<const int4*>(obj + t0));

    int s[TPO]  = {sA.x, sA.y, sA.z, sA.w};
    int rl[TPO] = {rA.x, rA.y, rA.z, rA.w};
    int o[TPO]  = {oA.x, oA.y, oA.z, oA.w};

    uint4 a[TPO];
#pragma unroll
    for (int j = 0; j < TPO; j++) {
        const uint4* sp = reinterpret_cast<const uint4*>(src + (size_t)s[j] * 32) + sub;
        a[j] = __ldg(sp);
    }

#pragma unroll
    for (int j = 0; j < TPO; j++) {
        const float4* rp = reinterpret_cast<const float4*>(rt + (size_t)rl[j] * 32 + sub * 8);
        float4 rA4 = __ldg(rp);
        float4 rB4 = __ldg(rp + 1);

        __half2 h0, h1, h2, h3;
        memcpy(&h0, &a[j].x, 4); memcpy(&h1, &a[j].y, 4);
        memcpy(&h2, &a[j].z, 4); memcpy(&h3, &a[j].w, 4);
        float2 f0 = __half22float2(h0), f1 = __half22float2(h1);
        float2 f2 = __half22float2(h2), f3 = __half22float2(h3);

        __half2 p0 = __floats2half2_rn(f0.x * rA4.x, f0.y * rA4.y);
        __half2 p1 = __floats2half2_rn(f1.x * rA4.z, f1.y * rA4.w);
        __half2 p2 = __floats2half2_rn(f2.x * rB4.x, f2.y * rB4.y);
        __half2 p3 = __floats2half2_rn(f3.x * rB4.z, f3.y * rB4.w);
        unsigned u0, u1, u2, u3;
        memcpy(&u0, &p0, 4); memcpy(&u1, &p1, 4);
        memcpy(&u2, &p2, 4); memcpy(&u3, &p3, 4);

        __half* d = dst + (size_t)o[j] * 32 + sub * 8;
        asm volatile("red.global.add.noftz.v4.f16x2 [%0], {%1, %2, %3, %4};"
                     :: "l"(d), "r"(u0), "r"(u1), "r"(u2), "r"(u3)
                     : "memory");
    }
}

#define H3_BLOCKS 15625

__global__ void __launch_bounds__(256)
hop3_kernel(const __half* __restrict__ src, float* __restrict__ dst,
            const int* __restrict__ subj, const int* __restrict__ rel,
            const int* __restrict__ obj, const float* __restrict__ rt,
            const int* __restrict__ n_hop, int hop) {
    if (*n_hop < hop) return;

    int tid  = threadIdx.x;
    int lane = tid & 31;
    int sub  = lane & 7;
    int oct  = (int)(((size_t)blockIdx.x * 256 + tid) >> 3);
    int t0   = oct * TPO;
    if (t0 >= N_T) return;

    int4 sA = __ldg(reinterpret_cast<const int4*>(subj + t0));
    int4 rA = __ldg(reinterpret_cast<const int4*>(rel + t0));
    int4 oA = __ldg(reinterpret_cast<const int4*>(obj + t0));

    int s[TPO]  = {sA.x, sA.y, sA.z, sA.w};
    int rl[TPO] = {rA.x, rA.y, rA.z, rA.w};
    int o[TPO]  = {oA.x, oA.y, oA.z, oA.w};

    uint2 a[TPO];
#pragma unroll
    for (int j = 0; j < TPO; j++) {
        const uint2* sp = reinterpret_cast<const uint2*>(src + (size_t)s[j] * 32) + sub;
        a[j] = __ldg(sp);
    }

#pragma unroll
    for (int j = 0; j < TPO; j++) {
        float4 r4 = __ldg(reinterpret_cast<const float4*>(rt + (size_t)rl[j] * 32 + sub * 4));
        __half2 h0, h1;
        memcpy(&h0, &a[j].x, 4); memcpy(&h1, &a[j].y, 4);
        float2 f0 = __half22float2(h0), f1 = __half22float2(h1);

        float m0 = f0.x * r4.x, m1 = f0.y * r4.y;
        float m2 = f1.x * r4.z, m3 = f1.y * r4.w;

        float* d = dst + (size_t)o[j] * 32 + sub * 4;
        asm volatile("red.global.add.v4.f32 [%0], {%1, %2, %3, %4};"
                     :: "l"(d), "f"(m0), "f"(m1), "f"(m2), "f"(m3)
                     : "memory");
    }
}

extern "C" void kernel_launch(void* const* d_in, const int* in_sizes, int n_in,
                              void* d_out, int out_size) {
    const float* x     = (const float*)d_in[0];
    const float* q     = (const float*)d_in[1];
    const int* subj    = (const int*)d_in[2];
    const int* rel     = (const int*)d_in[3];
    const int* obj     = (const int*)d_in[4];
    const float* W1    = (const float*)d_in[5];
    const float* b1    = (const float*)d_in[6];
    const float* W2    = (const float*)d_in[7];
    const float* b2    = (const float*)d_in[8];
    const float* W3    = (const float*)d_in[9];
    const float* b3    = (const float*)d_in[10];
    const int* n_hop   = (const int*)d_in[11];
    float* out         = (float*)d_out;

    __half *buf0h, *buf1h, *buf2h;
    float *buf3, *rt;
    cudaGetSymbolAddress((void**)&buf0h, g_buf0h);
    cudaGetSymbolAddress((void**)&buf1h, g_buf1h);
    cudaGetSymbolAddress((void**)&buf2h, g_buf2h);
    cudaGetSymbolAddress((void**)&buf3, g_buf3);
    cudaGetSymbolAddress((void**)&rt, g_rt);

    fused_pre_kernel<<<PRE_TOTAL_BLOCKS, 256>>>(
        x, q, W1, b1, W2, b2, W3, b3, buf0h, (float4*)buf1h, rt);

    // hop1 (fp16 RED) + appended zero of buf2h (fp16, 2M float4)
    hop12_kernel<<<H12_BLOCKS + Z16_BLOCKS, 256>>>(
        buf0h, buf1h, subj, rel, obj, rt + 0 * N_R * B_SZ, n_hop, 1,
        (float4*)buf2h, Z16_F4);

    // hop2 (fp16 RED) + appended zero of buf3 (fp32, 4M float4)
    hop12_kernel<<<H12_BLOCKS + Z32_BLOCKS, 256>>>(
        buf1h, buf2h, subj, rel, obj, rt + 1 * N_R * B_SZ, n_hop, 2,
        (float4*)buf3, Z32_F4);

    // hop3 (fp32 RED)
    hop3_kernel<<<H3_BLOCKS, 256>>>(
        buf2h, buf3, subj, rel, obj, rt + 2 * N_R * B_SZ, n_hop, 3);

    transpose_out_kernel<<<N_E / 32, dim3(32, 32)>>>(
        buf0h, buf1h, buf2h, buf3, n_hop, out);
}